// round 11
// baseline (speedup 1.0000x reference)
#include <cuda_runtime.h>
#include <cuda_bf16.h>
#include <mma.h>
#include <cstdint>

using namespace nvcuda;

#define NN    6144
#define INF   256
#define NH    4
#define DHD   64
#define HD    256
#define NCOLS 576

// GEMM tiling (round-6 geometry, int8 operands)
#define BM 128
#define BN 192
#define BK 64
#define STAGES 3
#define KITERS (NN / BK)     // 96
#define GTHREADS 256

#define A_LD    80           // int8 elems per row (64 + 16 pad)
#define B_LD    208          // int8 elems per row (192 + 16 pad)
#define A_BYTES (BM * A_LD)              // 10240
#define B_BYTES (BK * B_LD)              // 13312
#define STAGE_BYTES (A_BYTES + 2 * B_BYTES)   // 36864
#define SMEM_BYTES  (STAGES * STAGE_BYTES)    // 110592

// ---------------- scratch ----------------
__device__ float   g_h[NH][NN][DHD];        // h with bias
__device__ float   g_esrc[NH][NN];
__device__ float   g_esdst[NH][NN];
__device__ float   g_T[NH][DHD];
__device__ int8_t  g_adji[(size_t)NN * NN]; // 37.7 MB
__device__ int8_t  g_B1[NN][NCOLS];
__device__ int8_t  g_B2[NN][NCOLS];
__device__ float   g_s1[NCOLS];
__device__ float   g_s2[NCOLS];
__device__ int     g_Ci1[NN][NCOLS];
__device__ int     g_Ci2[NN][NCOLS];

// ---------------- helpers ----------------
__device__ __forceinline__ uint32_t smem_u32(const void* p) {
    uint32_t a;
    asm("{ .reg .u64 t; cvta.to.shared.u64 t, %1; cvt.u32.u64 %0, t; }" : "=r"(a) : "l"(p));
    return a;
}
__device__ __forceinline__ void cp16(uint32_t dst, const void* src) {
    asm volatile("cp.async.cg.shared.global [%0], [%1], 16;" :: "r"(dst), "l"(src) : "memory");
}

// ---------------- K1: merged  h = x@W + Wb (blocks 0..383)  ||  adj->int8 (rest) ----------------
#define HBLOCKS (NN / 64 * NH)     // 384
#define CVTBLKS ((int)((size_t)NN * NN / 2048))   // 18432

__global__ void k_pre(const float* __restrict__ x, const float* __restrict__ W,
                      const float* __restrict__ Wb, const int* __restrict__ adj) {
    __shared__ float sA[16][68];
    __shared__ float sB[16][64];
    const int bx = blockIdx.x;
    const int tid = threadIdx.x;

    if (bx >= HBLOCKS) {
        // ---- adj int32 -> int8 (0/1) ----
        size_t i = (size_t)(bx - HBLOCKS) * 2048 + (size_t)tid * 8;
        const int4* p = (const int4*)(adj + i);
        int4 a = p[0], b = p[1];
        uint32_t w0 = (a.x > 0 ? 1u : 0u) | ((a.y > 0 ? 1u : 0u) << 8)
                    | ((a.z > 0 ? 1u : 0u) << 16) | ((a.w > 0 ? 1u : 0u) << 24);
        uint32_t w1 = (b.x > 0 ? 1u : 0u) | ((b.y > 0 ? 1u : 0u) << 8)
                    | ((b.z > 0 ? 1u : 0u) << 16) | ((b.w > 0 ? 1u : 0u) << 24);
        *(uint2*)(&g_adji[i]) = make_uint2(w0, w1);
        return;
    }

    const int head = bx & 3;
    const int m0 = (bx >> 2) * 64;
    const int tx = tid & 15;
    const int ty = tid >> 4;

    float acc[4][4];
#pragma unroll
    for (int r = 0; r < 4; r++)
#pragma unroll
        for (int c = 0; c < 4; c++) acc[r][c] = 0.f;

    for (int k0 = 0; k0 < INF; k0 += 16) {
#pragma unroll
        for (int i = tid; i < 1024; i += 256) {
            int m = i >> 4, kk = i & 15;
            sA[kk][m] = x[(m0 + m) * INF + k0 + kk];
        }
#pragma unroll
        for (int i = tid; i < 1024; i += 256) {
            int kk = i >> 6, c = i & 63;
            sB[kk][c] = W[head * (INF * DHD) + (k0 + kk) * DHD + c];
        }
        __syncthreads();
#pragma unroll
        for (int kk = 0; kk < 16; kk++) {
            float4 av = *(const float4*)&sA[kk][ty * 4];
            float4 bv = *(const float4*)&sB[kk][tx * 4];
            float a4[4] = {av.x, av.y, av.z, av.w};
            float b4[4] = {bv.x, bv.y, bv.z, bv.w};
#pragma unroll
            for (int r = 0; r < 4; r++)
#pragma unroll
                for (int c = 0; c < 4; c++) acc[r][c] += a4[r] * b4[c];
        }
        __syncthreads();
    }
#pragma unroll
    for (int r = 0; r < 4; r++)
#pragma unroll
        for (int c = 0; c < 4; c++) {
            int d = tx * 4 + c;
            g_h[head][m0 + ty * 4 + r][d] = acc[r][c] + Wb[head * DHD + d];
        }
}

// ---------------- K2: scores (+ zero g_T) ----------------
__global__ void k_scores(const float* __restrict__ A, const float* __restrict__ Ab) {
    const int hd = blockIdx.x;
    if (hd == 0 && blockIdx.y == 0) ((float*)g_T)[threadIdx.x] = 0.f;
    const int wid = threadIdx.x >> 5, lane = threadIdx.x & 31;
    const int n = blockIdx.y * 8 + wid;
    const float h0 = g_h[hd][n][lane];
    const float h1 = g_h[hd][n][lane + 32];
    const float* Ah = A + hd * 2 * DHD;
    float ps = h0 * Ah[lane] + h1 * Ah[lane + 32];
    float pd = h0 * Ah[64 + lane] + h1 * Ah[96 + lane];
#pragma unroll
    for (int o = 16; o; o >>= 1) {
        ps += __shfl_xor_sync(0xffffffffu, ps, o);
        pd += __shfl_xor_sync(0xffffffffu, pd, o);
    }
    if (lane == 0) {
        g_esrc[hd][n]  = expf(ps + Ab[hd]);
        g_esdst[hd][n] = expf(pd);
    }
}

// ---------------- B value formula (shared by colmax + buildB) ----------------
__device__ __forceinline__ float b_value(int k, int col) {
    if (col < 256) {
        int hd = col >> 6, d = col & 63;
        return g_esdst[hd][k] * g_h[hd][k][d];
    } else if (col < 512) {
        int c2 = col - 256;
        return g_h[c2 >> 6][k][c2 & 63];
    } else if (col < 516) {
        return g_esdst[col - 512][k];
    } else if (col == 516) {
        return 1.0f;
    }
    return 0.0f;
}

// ---------------- K3a: per-column max -> scales ----------------
__global__ void k_colmax() {
    const int col = blockIdx.x;
    const int tid = threadIdx.x;
    float m = 0.f;
    for (int k = tid; k < NN; k += 256)
        m = fmaxf(m, fabsf(b_value(k, col)));
    __shared__ float red[256];
    red[tid] = m;
    __syncthreads();
    for (int o = 128; o; o >>= 1) {
        if (tid < o) red[tid] = fmaxf(red[tid], red[tid + o]);
        __syncthreads();
    }
    if (tid == 0) {
        float s1 = fmaxf(red[0], 1e-20f) / 127.0f;
        g_s1[col] = s1;
        g_s2[col] = s1 / 254.0f;
    }
}

// ---------------- K3b: merged  T-reduce || buildB (int8 quantize) ----------------
#define TBLOCKS 96
#define BBLKS   ((NN * NCOLS) / 256)

__global__ void k_T_buildB() {
    const int bx = blockIdx.x;
    const int tid = threadIdx.x;

    if (bx < TBLOCKS) {
        const int hd = bx / 24;
        const int base = (bx % 24) * 256;
        const int d = tid & 63, rp = tid >> 6;
        float s = 0.f;
        for (int r = rp; r < 256; r += 4) s += g_h[hd][base + r][d];
        __shared__ float red[256];
        red[tid] = s;
        __syncthreads();
        if (rp == 0)
            atomicAdd(&g_T[hd][d], red[d] + red[64 + d] + red[128 + d] + red[192 + d]);
        return;
    }

    const int idx = (bx - TBLOCKS) * 256 + tid;
    const int k = idx / NCOLS;
    const int col = idx - k * NCOLS;
    const float v = b_value(k, col);
    const float s1 = g_s1[col], s2 = g_s2[col];
    float q1 = rintf(v / s1);
    q1 = fminf(fmaxf(q1, -127.f), 127.f);
    float r = v - s1 * q1;
    float q2 = rintf(r / s2);
    q2 = fminf(fmaxf(q2, -127.f), 127.f);
    g_B1[k][col] = (int8_t)q1;
    g_B2[k][col] = (int8_t)q2;
}

// ---------------- K4: pipelined int8 wmma GEMM ----------------
__device__ __forceinline__ void load_stage(uint32_t sb, int s, int k0, int m0, int n0,
                                           const int8_t* __restrict__ adji, int tid) {
    const uint32_t a_base  = sb + s * STAGE_BYTES;
    const uint32_t b1_base = a_base + A_BYTES;
    const uint32_t b2_base = b1_base + B_BYTES;
    // A: 128 rows x 4 chunks(16B) = 512 / 256 = 2
#pragma unroll
    for (int q = 0; q < 2; q++) {
        int idx = tid + q * 256;
        int row = idx >> 2, c = idx & 3;
        cp16(a_base + row * A_LD + c * 16,
             adji + (size_t)(m0 + row) * NN + k0 + c * 16);
    }
    // B1/B2: 64 rows x 12 chunks = 768 each -> 3 passes each
#pragma unroll
    for (int q = 0; q < 3; q++) {
        int idx = tid + q * 256;
        int row = idx / 12, c = idx - row * 12;
        cp16(b1_base + row * B_LD + c * 16, &g_B1[k0 + row][n0 + c * 16]);
    }
#pragma unroll
    for (int q = 0; q < 3; q++) {
        int idx = tid + q * 256;
        int row = idx / 12, c = idx - row * 12;
        cp16(b2_base + row * B_LD + c * 16, &g_B2[k0 + row][n0 + c * 16]);
    }
    asm volatile("cp.async.commit_group;" ::: "memory");
}

__global__ void __launch_bounds__(GTHREADS, 1) k_attn_gemm(const int8_t* __restrict__ adji) {
    extern __shared__ char smem[];
    const uint32_t sb = smem_u32(smem);
    const int tid = threadIdx.x;
    const int wid = tid >> 5;
    const int wm = wid >> 2;          // 0..1  (64 rows)
    const int wn = wid & 3;           // 0..3  (48 cols)
    const int n0 = blockIdx.x * BN;
    const int m0 = blockIdx.y * BM;

    wmma::fragment<wmma::accumulator, 16, 16, 16, int> acc1[4][3], acc2[4][3];
#pragma unroll
    for (int r = 0; r < 4; r++)
#pragma unroll
        for (int c = 0; c < 3; c++) {
            wmma::fill_fragment(acc1[r][c], 0);
            wmma::fill_fragment(acc2[r][c], 0);
        }

    load_stage(sb, 0, 0, m0, n0, adji, tid);
    load_stage(sb, 1, BK, m0, n0, adji, tid);

    for (int i = 0; i < KITERS; i++) {
        const int s = i % STAGES;

        asm volatile("cp.async.wait_group 1;" ::: "memory");
        __syncthreads();
        if (i + 2 < KITERS)
            load_stage(sb, (i + 2) % STAGES, (i + 2) * BK, m0, n0, adji, tid);
        else
            asm volatile("cp.async.commit_group;" ::: "memory");

        const int8_t* sA  = (const int8_t*)(smem + s * STAGE_BYTES);
        const int8_t* sB1 = (const int8_t*)(smem + s * STAGE_BYTES + A_BYTES);
        const int8_t* sB2 = (const int8_t*)(smem + s * STAGE_BYTES + A_BYTES + B_BYTES);

#pragma unroll
        for (int kk = 0; kk < BK / 16; kk++) {
            wmma::fragment<wmma::matrix_a, 16, 16, 16, signed char, wmma::row_major> af[4];
#pragma unroll
            for (int r = 0; r < 4; r++)
                wmma::load_matrix_sync(af[r], sA + (wm * 64 + r * 16) * A_LD + kk * 16, A_LD);
#pragma unroll
            for (int c = 0; c < 3; c++) {
                wmma::fragment<wmma::matrix_b, 16, 16, 16, signed char, wmma::row_major> bf;
                wmma::load_matrix_sync(bf, sB1 + (kk * 16) * B_LD + wn * 48 + c * 16, B_LD);
#pragma unroll
                for (int r = 0; r < 4; r++) wmma::mma_sync(acc1[r][c], af[r], bf, acc1[r][c]);
                wmma::load_matrix_sync(bf, sB2 + (kk * 16) * B_LD + wn * 48 + c * 16, B_LD);
#pragma unroll
                for (int r = 0; r < 4; r++) wmma::mma_sync(acc2[r][c], af[r], bf, acc2[r][c]);
            }
        }
    }

#pragma unroll
    for (int r = 0; r < 4; r++)
#pragma unroll
        for (int c = 0; c < 3; c++) {
            wmma::store_matrix_sync(&g_Ci1[m0 + wm * 64 + r * 16][n0 + wn * 48 + c * 16],
                                    acc1[r][c], NCOLS, wmma::mem_row_major);
            wmma::store_matrix_sync(&g_Ci2[m0 + wm * 64 + r * 16][n0 + wn * 48 + c * 16],
                                    acc2[r][c], NCOLS, wmma::mem_row_major);
        }
}

// ---------------- K5: epilogue (dequant + combine) ----------------
__device__ __forceinline__ float deq(int n, int col) {
    return g_s1[col] * (float)g_Ci1[n][col] + g_s2[col] * (float)g_Ci2[n][col];
}

__global__ void k_epi(float* __restrict__ out) {
    const int idx = blockIdx.x * 256 + threadIdx.x;
    const int n = idx >> 8;
    const int c = idx & 255;
    const int hd = c >> 6, d = c & 63;
    const float es  = g_esrc[hd][n];
    const float u   = deq(n, hd * 64 + d);
    const float v   = deq(n, 256 + hd * 64 + d);
    const float w   = deq(n, 512 + hd);
    const float deg = deq(n, 516);
    const float Z = es * w + ((float)NN - deg);
    out[idx] = (es * u + g_T[hd][d] - v) / Z;
}

// ---------------- launch ----------------
extern "C" void kernel_launch(void* const* d_in, const int* in_sizes, int n_in,
                              void* d_out, int out_size) {
    const float* x = nullptr; const int* adj = nullptr;
    const float* W = nullptr; const float* Wb = nullptr;
    const float* A = nullptr; const float* Ab = nullptr;
    for (int i = 0; i < n_in; i++) {
        switch (in_sizes[i]) {
            case NN * INF:        x   = (const float*)d_in[i]; break;
            case NH * INF * DHD:  W   = (const float*)d_in[i]; break;
            case NH * DHD:        Wb  = (const float*)d_in[i]; break;
            case NH * 2 * DHD:    A   = (const float*)d_in[i]; break;
            case NH:              Ab  = (const float*)d_in[i]; break;
            default:
                if (in_sizes[i] == NN * NN) adj = (const int*)d_in[i];
                break;
        }
    }
    float* out = (float*)d_out;

    cudaFuncSetAttribute(k_attn_gemm, cudaFuncAttributeMaxDynamicSharedMemorySize, SMEM_BYTES);

    int8_t* adji_ptr = nullptr;
    cudaGetSymbolAddress((void**)&adji_ptr, g_adji);

    k_pre<<<HBLOCKS + CVTBLKS, 256>>>(x, W, Wb, adj);
    k_scores<<<dim3(NH, NN / 8), 256>>>(A, Ab);
    k_colmax<<<NCOLS, 256>>>();
    k_T_buildB<<<TBLOCKS + BBLKS, 256>>>();
    k_attn_gemm<<<dim3(NCOLS / BN, NN / BM), GTHREADS, SMEM_BYTES>>>(adji_ptr);
    k_epi<<<(NN * HD) / 256, 256>>>(out);
}

// round 12
// speedup vs baseline: 2.2748x; 2.2748x over previous
#include <cuda_runtime.h>
#include <cuda_bf16.h>
#include <mma.h>
#include <cstdint>

using namespace nvcuda;

#define NN    6144
#define INF   256
#define NH    4
#define DHD   64
#define HD    256
#define NCOLS 576

// GEMM tiling: 12 warps, warp tile 64x32, no spills (cap 170 regs)
#define BM 128
#define BN 192
#define BK 64
#define STAGES 3
#define KITERS (NN / BK)     // 96
#define GTHREADS 384

#define A_LD    72
#define B_LD    200
#define A_BYTES (BM * A_LD * 2)          // 18432
#define B_BYTES (BK * B_LD * 2)          // 25600
#define STAGE_BYTES (A_BYTES + 2 * B_BYTES)   // 69632
#define SMEM_BYTES  (STAGES * STAGE_BYTES)    // 208896

// ---------------- scratch ----------------
__device__ float          g_h[NH][NN][DHD];
__device__ float          g_esrc[NH][NN];
__device__ float          g_esdst[NH][NN];
__device__ float          g_T[NH][DHD];
__device__ __nv_bfloat16  g_adjb[(size_t)NN * NN];    // 75.5 MB, [m][k]
__device__ __nv_bfloat16  g_Bhi[NN][NCOLS];
__device__ __nv_bfloat16  g_Blo[NN][NCOLS];
__device__ float          g_C[NN][NCOLS];

// ---------------- helpers ----------------
__device__ __forceinline__ uint32_t smem_u32(const void* p) {
    uint32_t a;
    asm("{ .reg .u64 t; cvta.to.shared.u64 t, %1; cvt.u32.u64 %0, t; }" : "=r"(a) : "l"(p));
    return a;
}
__device__ __forceinline__ void cp16(uint32_t dst, const void* src) {
    asm volatile("cp.async.cg.shared.global [%0], [%1], 16;" :: "r"(dst), "l"(src) : "memory");
}
__device__ __forceinline__ uint32_t pack2(int a, int b) {
    return (a > 0 ? 0x3F80u : 0u) | ((b > 0 ? 0x3F80u : 0u) << 16);
}

// ---------------- K1: merged  h = x@W + Wb (blocks 0..383)  ||  adj->bf16 (rest) ----------------
#define HBLOCKS (NN / 64 * NH)     // 384
#define CVTBLKS ((int)((size_t)NN * NN / 2048))   // 18432

__global__ void k_pre(const float* __restrict__ x, const float* __restrict__ W,
                      const float* __restrict__ Wb, const int* __restrict__ adj) {
    __shared__ float sA[16][68];
    __shared__ float sB[16][64];
    const int bx = blockIdx.x;
    const int tid = threadIdx.x;

    if (bx >= HBLOCKS) {
        size_t i = (size_t)(bx - HBLOCKS) * 2048 + (size_t)tid * 8;
        const int4* p = (const int4*)(adj + i);
        int4 a = p[0], b = p[1];
        *(uint4*)(&g_adjb[i]) = make_uint4(pack2(a.x, a.y), pack2(a.z, a.w),
                                           pack2(b.x, b.y), pack2(b.z, b.w));
        return;
    }

    const int head = bx & 3;
    const int m0 = (bx >> 2) * 64;
    const int tx = tid & 15;
    const int ty = tid >> 4;

    float acc[4][4];
#pragma unroll
    for (int r = 0; r < 4; r++)
#pragma unroll
        for (int c = 0; c < 4; c++) acc[r][c] = 0.f;

    for (int k0 = 0; k0 < INF; k0 += 16) {
#pragma unroll
        for (int i = tid; i < 1024; i += 256) {
            int m = i >> 4, kk = i & 15;
            sA[kk][m] = x[(m0 + m) * INF + k0 + kk];
        }
#pragma unroll
        for (int i = tid; i < 1024; i += 256) {
            int kk = i >> 6, c = i & 63;
            sB[kk][c] = W[head * (INF * DHD) + (k0 + kk) * DHD + c];
        }
        __syncthreads();
#pragma unroll
        for (int kk = 0; kk < 16; kk++) {
            float4 av = *(const float4*)&sA[kk][ty * 4];
            float4 bv = *(const float4*)&sB[kk][tx * 4];
            float a4[4] = {av.x, av.y, av.z, av.w};
            float b4[4] = {bv.x, bv.y, bv.z, bv.w};
#pragma unroll
            for (int r = 0; r < 4; r++)
#pragma unroll
                for (int c = 0; c < 4; c++) acc[r][c] += a4[r] * b4[c];
        }
        __syncthreads();
    }
#pragma unroll
    for (int r = 0; r < 4; r++)
#pragma unroll
        for (int c = 0; c < 4; c++) {
            int d = tx * 4 + c;
            g_h[head][m0 + ty * 4 + r][d] = acc[r][c] + Wb[head * DHD + d];
        }
}

// ---------------- K2: scores (+ zero g_T) ----------------
__global__ void k_scores(const float* __restrict__ A, const float* __restrict__ Ab) {
    const int hd = blockIdx.x;
    if (hd == 0 && blockIdx.y == 0) ((float*)g_T)[threadIdx.x] = 0.f;
    const int wid = threadIdx.x >> 5, lane = threadIdx.x & 31;
    const int n = blockIdx.y * 8 + wid;
    const float h0 = g_h[hd][n][lane];
    const float h1 = g_h[hd][n][lane + 32];
    const float* Ah = A + hd * 2 * DHD;
    float ps = h0 * Ah[lane] + h1 * Ah[lane + 32];
    float pd = h0 * Ah[64 + lane] + h1 * Ah[96 + lane];
#pragma unroll
    for (int o = 16; o; o >>= 1) {
        ps += __shfl_xor_sync(0xffffffffu, ps, o);
        pd += __shfl_xor_sync(0xffffffffu, pd, o);
    }
    if (lane == 0) {
        g_esrc[hd][n]  = expf(ps + Ab[hd]);
        g_esdst[hd][n] = expf(pd);
    }
}

// ---------------- K3: merged  T-reduce || buildB ----------------
#define TBLOCKS 96
#define BBLKS   ((NN * NCOLS) / 256)

__global__ void k_T_buildB() {
    const int bx = blockIdx.x;
    const int tid = threadIdx.x;

    if (bx < TBLOCKS) {
        const int hd = bx / 24;
        const int base = (bx % 24) * 256;
        const int d = tid & 63, rp = tid >> 6;
        float s = 0.f;
        for (int r = rp; r < 256; r += 4) s += g_h[hd][base + r][d];
        __shared__ float red[256];
        red[tid] = s;
        __syncthreads();
        if (rp == 0)
            atomicAdd(&g_T[hd][d], red[d] + red[64 + d] + red[128 + d] + red[192 + d]);
        return;
    }

    const int idx = (bx - TBLOCKS) * 256 + tid;
    const int k = idx / NCOLS;
    const int col = idx - k * NCOLS;
    float v;
    if (col < 256) {
        int hd = col >> 6, d = col & 63;
        v = g_esdst[hd][k] * g_h[hd][k][d];
    } else if (col < 512) {
        int c2 = col - 256;
        v = g_h[c2 >> 6][k][c2 & 63];
    } else if (col < 516) {
        v = g_esdst[col - 512][k];
    } else if (col == 516) {
        v = 1.0f;
    } else {
        v = 0.0f;
    }
    __nv_bfloat16 hi = __float2bfloat16(v);
    float lo = v - __bfloat162float(hi);
    g_Bhi[k][col] = hi;
    g_Blo[k][col] = __float2bfloat16(lo);
}

// ---------------- K4: pipelined wmma GEMM, 12 warps, warp tile 64x32 ----------------
__device__ __forceinline__ void load_stage(uint32_t sb, int s, int k0, int m0, int n0,
                                           const __nv_bfloat16* __restrict__ adjb, int tid) {
    const uint32_t a_base  = sb + s * STAGE_BYTES;
    const uint32_t bh_base = a_base + A_BYTES;
    const uint32_t bl_base = bh_base + B_BYTES;
    // A: 128 rows x 8 chunks(16B) = 1024 chunks; 384 threads -> 2 full + 1 guarded pass
#pragma unroll
    for (int q = 0; q < 3; q++) {
        int idx = tid + q * GTHREADS;
        if (idx < 1024) {
            int row = idx >> 3, c = idx & 7;
            cp16(a_base + row * (A_LD * 2) + c * 16,
                 adjb + (size_t)(m0 + row) * NN + k0 + c * 8);
        }
    }
    // Bhi / Blo: 64 rows x 24 chunks = 1536 each -> 4 passes of 384
#pragma unroll
    for (int q = 0; q < 4; q++) {
        int idx = tid + q * GTHREADS;
        int row = idx / 24, c = idx - row * 24;
        cp16(bh_base + row * (B_LD * 2) + c * 16, &g_Bhi[k0 + row][n0 + c * 8]);
    }
#pragma unroll
    for (int q = 0; q < 4; q++) {
        int idx = tid + q * GTHREADS;
        int row = idx / 24, c = idx - row * 24;
        cp16(bl_base + row * (B_LD * 2) + c * 16, &g_Blo[k0 + row][n0 + c * 8]);
    }
    asm volatile("cp.async.commit_group;" ::: "memory");
}

__global__ void __launch_bounds__(GTHREADS, 1) k_attn_gemm(const __nv_bfloat16* __restrict__ adjb) {
    extern __shared__ char smem[];
    const uint32_t sb = smem_u32(smem);
    const int tid = threadIdx.x;
    const int wid = tid >> 5;
    const int wm = wid / 6;           // 0..1  (64 rows each)
    const int wn = wid % 6;           // 0..5  (32 cols each)
    const int n0 = blockIdx.x * BN;
    const int m0 = blockIdx.y * BM;

    wmma::fragment<wmma::accumulator, 16, 16, 16, float> acc[4][2];
#pragma unroll
    for (int r = 0; r < 4; r++)
#pragma unroll
        for (int c = 0; c < 2; c++) wmma::fill_fragment(acc[r][c], 0.f);

    load_stage(sb, 0, 0, m0, n0, adjb, tid);
    load_stage(sb, 1, BK, m0, n0, adjb, tid);

    for (int i = 0; i < KITERS; i++) {
        const int s = i % STAGES;

        asm volatile("cp.async.wait_group 1;" ::: "memory");
        __syncthreads();
        if (i + 2 < KITERS)
            load_stage(sb, (i + 2) % STAGES, (i + 2) * BK, m0, n0, adjb, tid);
        else
            asm volatile("cp.async.commit_group;" ::: "memory");

        const __nv_bfloat16* sA  = (const __nv_bfloat16*)(smem + s * STAGE_BYTES);
        const __nv_bfloat16* sBh = (const __nv_bfloat16*)(smem + s * STAGE_BYTES + A_BYTES);
        const __nv_bfloat16* sBl = (const __nv_bfloat16*)(smem + s * STAGE_BYTES + A_BYTES + B_BYTES);

#pragma unroll
        for (int kk = 0; kk < BK / 16; kk++) {
            wmma::fragment<wmma::matrix_a, 16, 16, 16, __nv_bfloat16, wmma::row_major> af[4];
#pragma unroll
            for (int r = 0; r < 4; r++)
                wmma::load_matrix_sync(af[r], sA + (wm * 64 + r * 16) * A_LD + kk * 16, A_LD);
#pragma unroll
            for (int c = 0; c < 2; c++) {
                wmma::fragment<wmma::matrix_b, 16, 16, 16, __nv_bfloat16, wmma::row_major> bf;
                wmma::load_matrix_sync(bf, sBh + (kk * 16) * B_LD + wn * 32 + c * 16, B_LD);
#pragma unroll
                for (int r = 0; r < 4; r++) wmma::mma_sync(acc[r][c], af[r], bf, acc[r][c]);
                wmma::load_matrix_sync(bf, sBl + (kk * 16) * B_LD + wn * 32 + c * 16, B_LD);
#pragma unroll
                for (int r = 0; r < 4; r++) wmma::mma_sync(acc[r][c], af[r], bf, acc[r][c]);
            }
        }
    }

#pragma unroll
    for (int r = 0; r < 4; r++)
#pragma unroll
        for (int c = 0; c < 2; c++)
            wmma::store_matrix_sync(&g_C[m0 + wm * 64 + r * 16][n0 + wn * 32 + c * 16],
                                    acc[r][c], NCOLS, wmma::mem_row_major);
}

// ---------------- K5: epilogue (float4) ----------------
__global__ void k_epi(float* __restrict__ out) {
    const int t = blockIdx.x * 256 + threadIdx.x;   // over NN*64 (4 cols each)
    const int n = t >> 6;
    const int c4 = (t & 63) * 4;                    // 0..252, 4-aligned
    const int hd = c4 >> 6;
    const float es  = g_esrc[hd][n];
    const float4 u  = *(const float4*)&g_C[n][c4];
    const float4 v  = *(const float4*)&g_C[n][256 + c4];
    const float w   = g_C[n][512 + hd];
    const float deg = g_C[n][516];
    const float invZ = 1.0f / (es * w + ((float)NN - deg));
    const float* Tp = &g_T[hd][c4 & 63];
    float4 o;
    o.x = (es * u.x + Tp[0] - v.x) * invZ;
    o.y = (es * u.y + Tp[1] - v.y) * invZ;
    o.z = (es * u.z + Tp[2] - v.z) * invZ;
    o.w = (es * u.w + Tp[3] - v.w) * invZ;
    *(float4*)&out[n * HD + c4] = o;
}

// ---------------- launch ----------------
extern "C" void kernel_launch(void* const* d_in, const int* in_sizes, int n_in,
                              void* d_out, int out_size) {
    const float* x = nullptr; const int* adj = nullptr;
    const float* W = nullptr; const float* Wb = nullptr;
    const float* A = nullptr; const float* Ab = nullptr;
    for (int i = 0; i < n_in; i++) {
        switch (in_sizes[i]) {
            case NN * INF:        x   = (const float*)d_in[i]; break;
            case NH * INF * DHD:  W   = (const float*)d_in[i]; break;
            case NH * DHD:        Wb  = (const float*)d_in[i]; break;
            case NH * 2 * DHD:    A   = (const float*)d_in[i]; break;
            case NH:              Ab  = (const float*)d_in[i]; break;
            default:
                if (in_sizes[i] == NN * NN) adj = (const int*)d_in[i];
                break;
        }
    }
    float* out = (float*)d_out;

    cudaFuncSetAttribute(k_attn_gemm, cudaFuncAttributeMaxDynamicSharedMemorySize, SMEM_BYTES);

    __nv_bfloat16* adjb_ptr = nullptr;
    cudaGetSymbolAddress((void**)&adjb_ptr, g_adjb);

    k_pre<<<HBLOCKS + CVTBLKS, 256>>>(x, W, Wb, adj);
    k_scores<<<dim3(NH, NN / 8), 256>>>(A, Ab);
    k_T_buildB<<<TBLOCKS + BBLKS, 256>>>();
    k_attn_gemm<<<dim3(NCOLS / BN, NN / BM), GTHREADS, SMEM_BYTES>>>(adjb_ptr);
    k_epi<<<(NN * 64) / 256, 256>>>(out);
}

// round 14
// speedup vs baseline: 2.3664x; 1.0403x over previous
#include <cuda_runtime.h>
#include <cuda_bf16.h>
#include <mma.h>
#include <cstdint>

using namespace nvcuda;

#define NN    6144
#define INF   256
#define NH    4
#define DHD   64
#define HD    256
#define NCOLS 576

// GEMM tiling (round-6 frozen optimum)
#define BM 128
#define BN 192
#define BK 64
#define STAGES 3
#define KITERS (NN / BK)     // 96
#define GTHREADS 256

#define A_LD    72
#define B_LD    200
#define A_BYTES (BM * A_LD * 2)          // 18432
#define B_BYTES (BK * B_LD * 2)          // 25600
#define STAGE_BYTES (A_BYTES + 2 * B_BYTES)   // 69632
#define SMEM_BYTES  (STAGES * STAGE_BYTES)    // 208896

// cvt distribution: 18432 units total, spread over 3 pre-GEMM kernels
#define CVT_TOTAL 18432
#define PRE_CVT   8192
#define SC_CVT    4096
#define TB_CVT    6144     // PRE+SC+TB == CVT_TOTAL

// ---------------- scratch ----------------
__device__ float          g_h[NH][NN][DHD];
__device__ float          g_esrc[NH][NN];
__device__ float          g_esdst[NH][NN];
__device__ float          g_T[NH][DHD];
__device__ __nv_bfloat16  g_adjb[(size_t)NN * NN];    // 75.5 MB, [m][k]
__device__ __nv_bfloat16  g_Bhi[NN][NCOLS];
__device__ __nv_bfloat16  g_Blo[NN][NCOLS];
__device__ float          g_C[NN][NCOLS];

// ---------------- helpers ----------------
__device__ __forceinline__ uint32_t smem_u32(const void* p) {
    uint32_t a;
    asm("{ .reg .u64 t; cvta.to.shared.u64 t, %1; cvt.u32.u64 %0, t; }" : "=r"(a) : "l"(p));
    return a;
}
__device__ __forceinline__ void cp16(uint32_t dst, const void* src) {
    asm volatile("cp.async.cg.shared.global [%0], [%1], 16;" :: "r"(dst), "l"(src) : "memory");
}
__device__ __forceinline__ uint32_t pack2(int a, int b) {
    return (a > 0 ? 0x3F80u : 0u) | ((b > 0 ? 0x3F80u : 0u) << 16);
}
// one cvt unit = 2048 int32 -> bf16 elements, by 256 threads
__device__ __forceinline__ void cvt_unit(int u, const int* __restrict__ adj, int tid) {
    size_t i = (size_t)u * 2048 + (size_t)tid * 8;
    const int4* p = (const int4*)(adj + i);
    int4 a = p[0], b = p[1];
    *(uint4*)(&g_adjb[i]) = make_uint4(pack2(a.x, a.y), pack2(a.z, a.w),
                                       pack2(b.x, b.y), pack2(b.z, b.w));
}

// ---------------- K1: merged  h = x@W + Wb (blocks 0..383)  ||  cvt units [0, PRE_CVT) ----------------
#define HBLOCKS (NN / 64 * NH)     // 384

__global__ void k_pre(const float* __restrict__ x, const float* __restrict__ W,
                      const float* __restrict__ Wb, const int* __restrict__ adj) {
    __shared__ float sA[16][68];
    __shared__ float sB[16][64];
    const int bx = blockIdx.x;
    const int tid = threadIdx.x;

    if (bx >= HBLOCKS) {
        cvt_unit(bx - HBLOCKS, adj, tid);
        return;
    }

    const int head = bx & 3;
    const int m0 = (bx >> 2) * 64;
    const int tx = tid & 15;
    const int ty = tid >> 4;

    float acc[4][4];
#pragma unroll
    for (int r = 0; r < 4; r++)
#pragma unroll
        for (int c = 0; c < 4; c++) acc[r][c] = 0.f;

    for (int k0 = 0; k0 < INF; k0 += 16) {
#pragma unroll
        for (int i = tid; i < 1024; i += 256) {
            int m = i >> 4, kk = i & 15;
            sA[kk][m] = x[(m0 + m) * INF + k0 + kk];
        }
#pragma unroll
        for (int i = tid; i < 1024; i += 256) {
            int kk = i >> 6, c = i & 63;
            sB[kk][c] = W[head * (INF * DHD) + (k0 + kk) * DHD + c];
        }
        __syncthreads();
#pragma unroll
        for (int kk = 0; kk < 16; kk++) {
            float4 av = *(const float4*)&sA[kk][ty * 4];
            float4 bv = *(const float4*)&sB[kk][tx * 4];
            float a4[4] = {av.x, av.y, av.z, av.w};
            float b4[4] = {bv.x, bv.y, bv.z, bv.w};
#pragma unroll
            for (int r = 0; r < 4; r++)
#pragma unroll
                for (int c = 0; c < 4; c++) acc[r][c] += a4[r] * b4[c];
        }
        __syncthreads();
    }
#pragma unroll
    for (int r = 0; r < 4; r++)
#pragma unroll
        for (int c = 0; c < 4; c++) {
            int d = tx * 4 + c;
            g_h[head][m0 + ty * 4 + r][d] = acc[r][c] + Wb[head * DHD + d];
        }
}

// ---------------- K2: scores (blocks 0..3071) || cvt units [PRE_CVT, PRE_CVT+SC_CVT) ----------------
#define SBLOCKS (NH * NN / 8)      // 3072

__global__ void k_scores(const float* __restrict__ A, const float* __restrict__ Ab,
                         const int* __restrict__ adj) {
    const int bx = blockIdx.x;
    const int tid = threadIdx.x;

    if (bx >= SBLOCKS) {
        cvt_unit(PRE_CVT + (bx - SBLOCKS), adj, tid);
        return;
    }

    const int hd = bx & 3;
    const int ny = bx >> 2;
    if (bx == 0) ((float*)g_T)[tid] = 0.f;
    const int wid = tid >> 5, lane = tid & 31;
    const int n = ny * 8 + wid;
    const float h0 = g_h[hd][n][lane];
    const float h1 = g_h[hd][n][lane + 32];
    const float* Ah = A + hd * 2 * DHD;
    float ps = h0 * Ah[lane] + h1 * Ah[lane + 32];
    float pd = h0 * Ah[64 + lane] + h1 * Ah[96 + lane];
#pragma unroll
    for (int o = 16; o; o >>= 1) {
        ps += __shfl_xor_sync(0xffffffffu, ps, o);
        pd += __shfl_xor_sync(0xffffffffu, pd, o);
    }
    if (lane == 0) {
        g_esrc[hd][n]  = expf(ps + Ab[hd]);
        g_esdst[hd][n] = expf(pd);
    }
}

// ---------------- K3: T-reduce (0..95) || buildB || cvt units [PRE_CVT+SC_CVT, 18432) ----------------
#define TBLOCKS 96
#define BBLKS   ((NN * NCOLS) / 256)   // 13824

__global__ void k_T_buildB(const int* __restrict__ adj) {
    const int bx = blockIdx.x;
    const int tid = threadIdx.x;

    if (bx < TBLOCKS) {
        const int hd = bx / 24;
        const int base = (bx % 24) * 256;
        const int d = tid & 63, rp = tid >> 6;
        float s = 0.f;
        for (int r = rp; r < 256; r += 4) s += g_h[hd][base + r][d];
        __shared__ float red[256];
        red[tid] = s;
        __syncthreads();
        if (rp == 0)
            atomicAdd(&g_T[hd][d], red[d] + red[64 + d] + red[128 + d] + red[192 + d]);
        return;
    }
    if (bx >= TBLOCKS + BBLKS) {
        cvt_unit(PRE_CVT + SC_CVT + (bx - TBLOCKS - BBLKS), adj, tid);
        return;
    }

    const int idx = (bx - TBLOCKS) * 256 + tid;
    const int k = idx / NCOLS;
    const int col = idx - k * NCOLS;
    float v;
    if (col < 256) {
        int hd = col >> 6, d = col & 63;
        v = g_esdst[hd][k] * g_h[hd][k][d];
    } else if (col < 512) {
        int c2 = col - 256;
        v = g_h[c2 >> 6][k][c2 & 63];
    } else if (col < 516) {
        v = g_esdst[col - 512][k];
    } else if (col == 516) {
        v = 1.0f;
    } else {
        v = 0.0f;
    }
    __nv_bfloat16 hi = __float2bfloat16(v);
    float lo = v - __bfloat162float(hi);
    g_Bhi[k][col] = hi;
    g_Blo[k][col] = __float2bfloat16(lo);
}

// ---------------- K4: pipelined wmma GEMM (round-6 frozen, byte-identical) ----------------
__device__ __forceinline__ void load_stage(uint32_t sb, int s, int k0, int m0, int n0,
                                           const __nv_bfloat16* __restrict__ adjb, int tid) {
    const uint32_t a_base  = sb + s * STAGE_BYTES;
    const uint32_t bh_base = a_base + A_BYTES;
    const uint32_t bl_base = bh_base + B_BYTES;
#pragma unroll
    for (int q = 0; q < 4; q++) {
        int idx = tid + q * 256;
        int row = idx >> 3, c = idx & 7;
        cp16(a_base + row * (A_LD * 2) + c * 16,
             adjb + (size_t)(m0 + row) * NN + k0 + c * 8);
    }
#pragma unroll
    for (int q = 0; q < 6; q++) {
        int idx = tid + q * 256;
        int row = idx / 24, c = idx - row * 24;
        cp16(bh_base + row * (B_LD * 2) + c * 16, &g_Bhi[k0 + row][n0 + c * 8]);
    }
#pragma unroll
    for (int q = 0; q < 6; q++) {
        int idx = tid + q * 256;
        int row = idx / 24, c = idx - row * 24;
        cp16(bl_base + row * (B_LD * 2) + c * 16, &g_Blo[k0 + row][n0 + c * 8]);
    }
    asm volatile("cp.async.commit_group;" ::: "memory");
}

__global__ void __launch_bounds__(GTHREADS, 1) k_attn_gemm(const __nv_bfloat16* __restrict__ adjb) {
    extern __shared__ char smem[];
    const uint32_t sb = smem_u32(smem);
    const int tid = threadIdx.x;
    const int wid = tid >> 5;
    const int wm = wid >> 2;          // 0..1  (64 rows each)
    const int wn = wid & 3;           // 0..3  (48 cols each)
    const int n0 = blockIdx.x * BN;
    const int m0 = blockIdx.y * BM;

    wmma::fragment<wmma::accumulator, 16, 16, 16, float> acc[4][3];
#pragma unroll
    for (int r = 0; r < 4; r++)
#pragma unroll
        for (int c = 0; c < 3; c++) wmma::fill_fragment(acc[r][c], 0.f);

    load_stage(sb, 0, 0, m0, n0, adjb, tid);
    load_stage(sb, 1, BK, m0, n0, adjb, tid);

    for (int i = 0; i < KITERS; i++) {
        const int s = i % STAGES;

        asm volatile("cp.async.wait_group 1;" ::: "memory");
        __syncthreads();
        if (i + 2 < KITERS)
            load_stage(sb, (i + 2) % STAGES, (i + 2) * BK, m0, n0, adjb, tid);
        else
            asm volatile("cp.async.commit_group;" ::: "memory");

        const __nv_bfloat16* sA  = (const __nv_bfloat16*)(smem + s * STAGE_BYTES);
        const __nv_bfloat16* sBh = (const __nv_bfloat16*)(smem + s * STAGE_BYTES + A_BYTES);
        const __nv_bfloat16* sBl = (const __nv_bfloat16*)(smem + s * STAGE_BYTES + A_BYTES + B_BYTES);

#pragma unroll
        for (int kk = 0; kk < BK / 16; kk++) {
            wmma::fragment<wmma::matrix_a, 16, 16, 16, __nv_bfloat16, wmma::row_major> af[4];
#pragma unroll
            for (int r = 0; r < 4; r++)
                wmma::load_matrix_sync(af[r], sA + (wm * 64 + r * 16) * A_LD + kk * 16, A_LD);
#pragma unroll
            for (int c = 0; c < 3; c++) {
                wmma::fragment<wmma::matrix_b, 16, 16, 16, __nv_bfloat16, wmma::row_major> bf;
                wmma::load_matrix_sync(bf, sBh + (kk * 16) * B_LD + wn * 48 + c * 16, B_LD);
#pragma unroll
                for (int r = 0; r < 4; r++) wmma::mma_sync(acc[r][c], af[r], bf, acc[r][c]);
                wmma::load_matrix_sync(bf, sBl + (kk * 16) * B_LD + wn * 48 + c * 16, B_LD);
#pragma unroll
                for (int r = 0; r < 4; r++) wmma::mma_sync(acc[r][c], af[r], bf, acc[r][c]);
            }
        }
    }

#pragma unroll
    for (int r = 0; r < 4; r++)
#pragma unroll
        for (int c = 0; c < 3; c++)
            wmma::store_matrix_sync(&g_C[m0 + wm * 64 + r * 16][n0 + wn * 48 + c * 16],
                                    acc[r][c], NCOLS, wmma::mem_row_major);
}

// ---------------- K5: epilogue (float4) ----------------
__global__ void k_epi(float* __restrict__ out) {
    const int t = blockIdx.x * 256 + threadIdx.x;   // over NN*64 (4 cols each)
    const int n = t >> 6;
    const int c4 = (t & 63) * 4;
    const int hd = c4 >> 6;
    const float es  = g_esrc[hd][n];
    const float4 u  = *(const float4*)&g_C[n][c4];
    const float4 v  = *(const float4*)&g_C[n][256 + c4];
    const float w   = g_C[n][512 + hd];
    const float deg = g_C[n][516];
    const float invZ = 1.0f / (es * w + ((float)NN - deg));
    const float* Tp = &g_T[hd][c4 & 63];
    float4 o;
    o.x = (es * u.x + Tp[0] - v.x) * invZ;
    o.y = (es * u.y + Tp[1] - v.y) * invZ;
    o.z = (es * u.z + Tp[2] - v.z) * invZ;
    o.w = (es * u.w + Tp[3] - v.w) * invZ;
    *(float4*)&out[n * HD + c4] = o;
}

// ---------------- launch ----------------
extern "C" void kernel_launch(void* const* d_in, const int* in_sizes, int n_in,
                              void* d_out, int out_size) {
    const float* x = nullptr; const int* adj = nullptr;
    const float* W = nullptr; const float* Wb = nullptr;
    const float* A = nullptr; const float* Ab = nullptr;
    for (int i = 0; i < n_in; i++) {
        switch (in_sizes[i]) {
            case NN * INF:        x   = (const float*)d_in[i]; break;
            case NH * INF * DHD:  W   = (const float*)d_in[i]; break;
            case NH * DHD:        Wb  = (const float*)d_in[i]; break;
            case NH * 2 * DHD:    A   = (const float*)d_in[i]; break;
            case NH:              Ab  = (const float*)d_in[i]; break;
            default:
                if (in_sizes[i] == NN * NN) adj = (const int*)d_in[i];
                break;
        }
    }
    float* out = (float*)d_out;

    cudaFuncSetAttribute(k_attn_gemm, cudaFuncAttributeMaxDynamicSharedMemorySize, SMEM_BYTES);

    __nv_bfloat16* adjb_ptr = nullptr;
    cudaGetSymbolAddress((void**)&adjb_ptr, g_adjb);

    k_pre<<<HBLOCKS + PRE_CVT, 256>>>(x, W, Wb, adj);
    k_scores<<<SBLOCKS + SC_CVT, 256>>>(A, Ab, adj);
    k_T_buildB<<<TBLOCKS + BBLKS + TB_CVT, 256>>>(adj);
    k_attn_gemm<<<dim3(NCOLS / BN, NN / BM), GTHREADS, SMEM_BYTES>>>(adjb_ptr);
    k_epi<<<(NN * 64) / 256, 256>>>(out);
}

// round 15
// speedup vs baseline: 3.5512x; 1.5007x over previous
#include <cuda_runtime.h>
#include <cuda_bf16.h>
#include <mma.h>
#include <cstdint>

using namespace nvcuda;

#define NN    6144
#define INF   256
#define NH    4
#define DHD   64
#define HD    256
#define NCOLS 576

// GEMM tiling (round-6 frozen optimum)
#define BM 128
#define BN 192
#define BK 64
#define STAGES 3
#define KITERS (NN / BK)     // 96
#define GTHREADS 256

#define A_LD    72
#define B_LD    200
#define A_BYTES (BM * A_LD * 2)          // 18432
#define B_BYTES (BK * B_LD * 2)          // 25600
#define STAGE_BYTES (A_BYTES + 2 * B_BYTES)   // 69632
#define SMEM_BYTES  (STAGES * STAGE_BYTES)    // 208896

// cvt distribution: 18432 units total, spread over 3 pre-GEMM kernels
#define CVT_TOTAL 18432
#define PRE_CVT   8192
#define SC_CVT    4096
#define TB_CVT    6144     // PRE+SC+TB == CVT_TOTAL

// ---------------- scratch ----------------
__device__ float          g_h[NH][NN][DHD];
__device__ float          g_esrc[NH][NN];
__device__ float          g_esdst[NH][NN];
__device__ float          g_T[NH][DHD];
__device__ __nv_bfloat16  g_adjb[(size_t)NN * NN];    // 75.5 MB, [m][k]
__device__ __nv_bfloat16  g_Bhi[NN][NCOLS];
__device__ __nv_bfloat16  g_Blo[NN][NCOLS];
__device__ float          g_C[NN][NCOLS];

// ---------------- helpers ----------------
__device__ __forceinline__ uint32_t smem_u32(const void* p) {
    uint32_t a;
    asm("{ .reg .u64 t; cvta.to.shared.u64 t, %1; cvt.u32.u64 %0, t; }" : "=r"(a) : "l"(p));
    return a;
}
__device__ __forceinline__ void cp16(uint32_t dst, const void* src) {
    asm volatile("cp.async.cg.shared.global [%0], [%1], 16;" :: "r"(dst), "l"(src) : "memory");
}
__device__ __forceinline__ uint32_t pack2(int a, int b) {
    return (a > 0 ? 0x3F80u : 0u) | ((b > 0 ? 0x3F80u : 0u) << 16);
}
// one cvt unit = 2048 int32 -> bf16 elements, by 256 threads
__device__ __forceinline__ void cvt_unit(int u, const int* __restrict__ adj, int tid) {
    size_t i = (size_t)u * 2048 + (size_t)tid * 8;
    const int4* p = (const int4*)(adj + i);
    int4 a = p[0], b = p[1];
    *(uint4*)(&g_adjb[i]) = make_uint4(pack2(a.x, a.y), pack2(a.z, a.w),
                                       pack2(b.x, b.y), pack2(b.z, b.w));
}

// ---------------- K1: merged  h = x@W + Wb (blocks 0..383)  ||  cvt units [0, PRE_CVT) ----------------
#define HBLOCKS (NN / 64 * NH)     // 384

__global__ void k_pre(const float* __restrict__ x, const float* __restrict__ W,
                      const float* __restrict__ Wb, const int* __restrict__ adj) {
    __shared__ float sA[16][68];
    __shared__ float sB[16][64];
    const int bx = blockIdx.x;
    const int tid = threadIdx.x;

    if (bx >= HBLOCKS) {
        cvt_unit(bx - HBLOCKS, adj, tid);
        return;
    }

    const int head = bx & 3;
    const int m0 = (bx >> 2) * 64;
    const int tx = tid & 15;
    const int ty = tid >> 4;

    float acc[4][4];
#pragma unroll
    for (int r = 0; r < 4; r++)
#pragma unroll
        for (int c = 0; c < 4; c++) acc[r][c] = 0.f;

    for (int k0 = 0; k0 < INF; k0 += 16) {
#pragma unroll
        for (int i = tid; i < 1024; i += 256) {
            int m = i >> 4, kk = i & 15;
            sA[kk][m] = x[(m0 + m) * INF + k0 + kk];
        }
#pragma unroll
        for (int i = tid; i < 1024; i += 256) {
            int kk = i >> 6, c = i & 63;
            sB[kk][c] = W[head * (INF * DHD) + (k0 + kk) * DHD + c];
        }
        __syncthreads();
#pragma unroll
        for (int kk = 0; kk < 16; kk++) {
            float4 av = *(const float4*)&sA[kk][ty * 4];
            float4 bv = *(const float4*)&sB[kk][tx * 4];
            float a4[4] = {av.x, av.y, av.z, av.w};
            float b4[4] = {bv.x, bv.y, bv.z, bv.w};
#pragma unroll
            for (int r = 0; r < 4; r++)
#pragma unroll
                for (int c = 0; c < 4; c++) acc[r][c] += a4[r] * b4[c];
        }
        __syncthreads();
    }
#pragma unroll
    for (int r = 0; r < 4; r++)
#pragma unroll
        for (int c = 0; c < 4; c++) {
            int d = tx * 4 + c;
            g_h[head][m0 + ty * 4 + r][d] = acc[r][c] + Wb[head * DHD + d];
        }
}

// ---------------- K2: scores (blocks 0..3071) || cvt units [PRE_CVT, PRE_CVT+SC_CVT) ----------------
#define SBLOCKS (NH * NN / 8)      // 3072

__global__ void k_scores(const float* __restrict__ A, const float* __restrict__ Ab,
                         const int* __restrict__ adj) {
    const int bx = blockIdx.x;
    const int tid = threadIdx.x;

    if (bx >= SBLOCKS) {
        cvt_unit(PRE_CVT + (bx - SBLOCKS), adj, tid);
        return;
    }

    const int hd = bx & 3;
    const int ny = bx >> 2;
    if (bx == 0) ((float*)g_T)[tid] = 0.f;
    const int wid = tid >> 5, lane = tid & 31;
    const int n = ny * 8 + wid;
    const float h0 = g_h[hd][n][lane];
    const float h1 = g_h[hd][n][lane + 32];
    const float* Ah = A + hd * 2 * DHD;
    float ps = h0 * Ah[lane] + h1 * Ah[lane + 32];
    float pd = h0 * Ah[64 + lane] + h1 * Ah[96 + lane];
#pragma unroll
    for (int o = 16; o; o >>= 1) {
        ps += __shfl_xor_sync(0xffffffffu, ps, o);
        pd += __shfl_xor_sync(0xffffffffu, pd, o);
    }
    if (lane == 0) {
        g_esrc[hd][n]  = expf(ps + Ab[hd]);
        g_esdst[hd][n] = expf(pd);
    }
}

// ---------------- K3: T-reduce (0..95) || buildB || cvt units [PRE_CVT+SC_CVT, 18432) ----------------
#define TBLOCKS 96
#define BBLKS   ((NN * NCOLS) / 256)   // 13824

__global__ void k_T_buildB(const int* __restrict__ adj) {
    const int bx = blockIdx.x;
    const int tid = threadIdx.x;

    if (bx < TBLOCKS) {
        const int hd = bx / 24;
        const int base = (bx % 24) * 256;
        const int d = tid & 63, rp = tid >> 6;
        float s = 0.f;
        for (int r = rp; r < 256; r += 4) s += g_h[hd][base + r][d];
        __shared__ float red[256];
        red[tid] = s;
        __syncthreads();
        if (rp == 0)
            atomicAdd(&g_T[hd][d], red[d] + red[64 + d] + red[128 + d] + red[192 + d]);
        return;
    }
    if (bx >= TBLOCKS + BBLKS) {
        cvt_unit(PRE_CVT + SC_CVT + (bx - TBLOCKS - BBLKS), adj, tid);
        return;
    }

    const int idx = (bx - TBLOCKS) * 256 + tid;
    const int k = idx / NCOLS;
    const int col = idx - k * NCOLS;
    float v;
    if (col < 256) {
        int hd = col >> 6, d = col & 63;
        v = g_esdst[hd][k] * g_h[hd][k][d];
    } else if (col < 512) {
        int c2 = col - 256;
        v = g_h[c2 >> 6][k][c2 & 63];
    } else if (col < 516) {
        v = g_esdst[col - 512][k];
    } else if (col == 516) {
        v = 1.0f;
    } else {
        v = 0.0f;
    }
    __nv_bfloat16 hi = __float2bfloat16(v);
    float lo = v - __bfloat162float(hi);
    g_Bhi[k][col] = hi;
    g_Blo[k][col] = __float2bfloat16(lo);
}

// ---------------- K4: pipelined wmma GEMM (round-6 frozen, byte-identical) ----------------
__device__ __forceinline__ void load_stage(uint32_t sb, int s, int k0, int m0, int n0,
                                           const __nv_bfloat16* __restrict__ adjb, int tid) {
    const uint32_t a_base  = sb + s * STAGE_BYTES;
    const uint32_t bh_base = a_base + A_BYTES;
    const uint32_t bl_base = bh_base + B_BYTES;
#pragma unroll
    for (int q = 0; q < 4; q++) {
        int idx = tid + q * 256;
        int row = idx >> 3, c = idx & 7;
        cp16(a_base + row * (A_LD * 2) + c * 16,
             adjb + (size_t)(m0 + row) * NN + k0 + c * 8);
    }
#pragma unroll
    for (int q = 0; q < 6; q++) {
        int idx = tid + q * 256;
        int row = idx / 24, c = idx - row * 24;
        cp16(bh_base + row * (B_LD * 2) + c * 16, &g_Bhi[k0 + row][n0 + c * 8]);
    }
#pragma unroll
    for (int q = 0; q < 6; q++) {
        int idx = tid + q * 256;
        int row = idx / 24, c = idx - row * 24;
        cp16(bl_base + row * (B_LD * 2) + c * 16, &g_Blo[k0 + row][n0 + c * 8]);
    }
    asm volatile("cp.async.commit_group;" ::: "memory");
}

__global__ void __launch_bounds__(GTHREADS, 1) k_attn_gemm(const __nv_bfloat16* __restrict__ adjb) {
    extern __shared__ char smem[];
    const uint32_t sb = smem_u32(smem);
    const int tid = threadIdx.x;
    const int wid = tid >> 5;
    const int wm = wid >> 2;          // 0..1  (64 rows each)
    const int wn = wid & 3;           // 0..3  (48 cols each)
    const int n0 = blockIdx.x * BN;
    const int m0 = blockIdx.y * BM;

    wmma::fragment<wmma::accumulator, 16, 16, 16, float> acc[4][3];
#pragma unroll
    for (int r = 0; r < 4; r++)
#pragma unroll
        for (int c = 0; c < 3; c++) wmma::fill_fragment(acc[r][c], 0.f);

    load_stage(sb, 0, 0, m0, n0, adjb, tid);
    load_stage(sb, 1, BK, m0, n0, adjb, tid);

    for (int i = 0; i < KITERS; i++) {
        const int s = i % STAGES;

        asm volatile("cp.async.wait_group 1;" ::: "memory");
        __syncthreads();
        if (i + 2 < KITERS)
            load_stage(sb, (i + 2) % STAGES, (i + 2) * BK, m0, n0, adjb, tid);
        else
            asm volatile("cp.async.commit_group;" ::: "memory");

        const __nv_bfloat16* sA  = (const __nv_bfloat16*)(smem + s * STAGE_BYTES);
        const __nv_bfloat16* sBh = (const __nv_bfloat16*)(smem + s * STAGE_BYTES + A_BYTES);
        const __nv_bfloat16* sBl = (const __nv_bfloat16*)(smem + s * STAGE_BYTES + A_BYTES + B_BYTES);

#pragma unroll
        for (int kk = 0; kk < BK / 16; kk++) {
            wmma::fragment<wmma::matrix_a, 16, 16, 16, __nv_bfloat16, wmma::row_major> af[4];
#pragma unroll
            for (int r = 0; r < 4; r++)
                wmma::load_matrix_sync(af[r], sA + (wm * 64 + r * 16) * A_LD + kk * 16, A_LD);
#pragma unroll
            for (int c = 0; c < 3; c++) {
                wmma::fragment<wmma::matrix_b, 16, 16, 16, __nv_bfloat16, wmma::row_major> bf;
                wmma::load_matrix_sync(bf, sBh + (kk * 16) * B_LD + wn * 48 + c * 16, B_LD);
#pragma unroll
                for (int r = 0; r < 4; r++) wmma::mma_sync(acc[r][c], af[r], bf, acc[r][c]);
                wmma::load_matrix_sync(bf, sBl + (kk * 16) * B_LD + wn * 48 + c * 16, B_LD);
#pragma unroll
                for (int r = 0; r < 4; r++) wmma::mma_sync(acc[r][c], af[r], bf, acc[r][c]);
            }
        }
    }

#pragma unroll
    for (int r = 0; r < 4; r++)
#pragma unroll
        for (int c = 0; c < 3; c++)
            wmma::store_matrix_sync(&g_C[m0 + wm * 64 + r * 16][n0 + wn * 48 + c * 16],
                                    acc[r][c], NCOLS, wmma::mem_row_major);
}

// ---------------- K5: epilogue (float4) ----------------
__global__ void k_epi(float* __restrict__ out) {
    const int t = blockIdx.x * 256 + threadIdx.x;   // over NN*64 (4 cols each)
    const int n = t >> 6;
    const int c4 = (t & 63) * 4;
    const int hd = c4 >> 6;
    const float es  = g_esrc[hd][n];
    const float4 u  = *(const float4*)&g_C[n][c4];
    const float4 v  = *(const float4*)&g_C[n][256 + c4];
    const float w   = g_C[n][512 + hd];
    const float deg = g_C[n][516];
    const float invZ = 1.0f / (es * w + ((float)NN - deg));
    const float* Tp = &g_T[hd][c4 & 63];
    float4 o;
    o.x = (es * u.x + Tp[0] - v.x) * invZ;
    o.y = (es * u.y + Tp[1] - v.y) * invZ;
    o.z = (es * u.z + Tp[2] - v.z) * invZ;
    o.w = (es * u.w + Tp[3] - v.w) * invZ;
    *(float4*)&out[n * HD + c4] = o;
}

// ---------------- launch ----------------
extern "C" void kernel_launch(void* const* d_in, const int* in_sizes, int n_in,
                              void* d_out, int out_size) {
    const float* x = nullptr; const int* adj = nullptr;
    const float* W = nullptr; const float* Wb = nullptr;
    const float* A = nullptr; const float* Ab = nullptr;
    for (int i = 0; i < n_in; i++) {
        switch (in_sizes[i]) {
            case NN * INF:        x   = (const float*)d_in[i]; break;
            case NH * INF * DHD:  W   = (const float*)d_in[i]; break;
            case NH * DHD:        Wb  = (const float*)d_in[i]; break;
            case NH * 2 * DHD:    A   = (const float*)d_in[i]; break;
            case NH:              Ab  = (const float*)d_in[i]; break;
            default:
                if (in_sizes[i] == NN * NN) adj = (const int*)d_in[i];
                break;
        }
    }
    float* out = (float*)d_out;

    cudaFuncSetAttribute(k_attn_gemm, cudaFuncAttributeMaxDynamicSharedMemorySize, SMEM_BYTES);

    __nv_bfloat16* adjb_ptr = nullptr;
    cudaGetSymbolAddress((void**)&adjb_ptr, g_adjb);

    k_pre<<<HBLOCKS + PRE_CVT, 256>>>(x, W, Wb, adj);
    k_scores<<<SBLOCKS + SC_CVT, 256>>>(A, Ab, adj);
    k_T_buildB<<<TBLOCKS + BBLKS + TB_CVT, 256>>>(adj);
    k_attn_gemm<<<dim3(NCOLS / BN, NN / BM), GTHREADS, SMEM_BYTES>>>(adjb_ptr);
    k_epi<<<(NN * 64) / 256, 256>>>(out);
}

// round 16
// speedup vs baseline: 3.6355x; 1.0237x over previous
#include <cuda_runtime.h>
#include <cuda_bf16.h>
#include <mma.h>
#include <cstdint>

using namespace nvcuda;

#define NN    6144
#define INF   256
#define NH    4
#define DHD   64
#define HD    256
#define NCOLS 576
#define MROWS (NN + 128)     // extra m-tile: row 6144 = ones (T row), 6145.. = zeros

// GEMM tiling (round-6 frozen optimum)
#define BM 128
#define BN 192
#define BK 64
#define STAGES 3
#define KITERS (NN / BK)     // 96
#define GTHREADS 256

#define A_LD    72
#define B_LD    200
#define A_BYTES (BM * A_LD * 2)          // 18432
#define B_BYTES (BK * B_LD * 2)          // 25600
#define STAGE_BYTES (A_BYTES + 2 * B_BYTES)   // 69632
#define SMEM_BYTES  (STAGES * STAGE_BYTES)    // 208896

// k_pre block partition
#define HBLOCKS  (NN / 64 * NH)                      // 384 h-gemm blocks
#define CVT_TOTAL ((int)((size_t)NN * NN / 2048))    // 18432 cvt units
#define FILL_TOTAL ((128 * NN) / 2048)               // 384 fill units (rows 6144..6271)

// ---------------- scratch ----------------
__device__ float          g_esrc[NH][NN];
__device__ __nv_bfloat16  g_adjb[(size_t)MROWS * NN];   // 77 MB, [m][k]
__device__ __nv_bfloat16  g_Bhi[NN][NCOLS];   // cols 517..575 never written: stay zero-init
__device__ __nv_bfloat16  g_Blo[NN][NCOLS];
__device__ float          g_C[MROWS][NCOLS];

// ---------------- helpers ----------------
__device__ __forceinline__ uint32_t smem_u32(const void* p) {
    uint32_t a;
    asm("{ .reg .u64 t; cvta.to.shared.u64 t, %1; cvt.u32.u64 %0, t; }" : "=r"(a) : "l"(p));
    return a;
}
__device__ __forceinline__ void cp16(uint32_t dst, const void* src) {
    asm volatile("cp.async.cg.shared.global [%0], [%1], 16;" :: "r"(dst), "l"(src) : "memory");
}
__device__ __forceinline__ uint32_t pack2(int a, int b) {
    return (a > 0 ? 0x3F80u : 0u) | ((b > 0 ? 0x3F80u : 0u) << 16);
}
__device__ __forceinline__ uint32_t packbf2(float a, float b) {
    uint32_t ua = __bfloat16_as_ushort(__float2bfloat16(a));
    uint32_t ub = __bfloat16_as_ushort(__float2bfloat16(b));
    return ua | (ub << 16);
}

// ---------------- K1: fused  h-gemm+scores+buildB  ||  adj->bf16 cvt  ||  ones-row fill ----------------
__global__ void k_pre(const float* __restrict__ x, const float* __restrict__ W,
                      const float* __restrict__ Wb, const float* __restrict__ A,
                      const float* __restrict__ Ab, const int* __restrict__ adj) {
    __shared__ float sA[16][68];
    __shared__ float sB[16][64];
    __shared__ float sps[64][17];
    __shared__ float spd[64][17];
    __shared__ float sesd[64];
    const int bx = blockIdx.x;
    const int tid = threadIdx.x;

    if (bx >= HBLOCKS) {
        const int u = bx - HBLOCKS;
        if (u < CVT_TOTAL) {
            // ---- adj int32 -> bf16, rows 0..6143 ----
            size_t i = (size_t)u * 2048 + (size_t)tid * 8;
            const int4* p = (const int4*)(adj + i);
            int4 a = p[0], b = p[1];
            *(uint4*)(&g_adjb[i]) = make_uint4(pack2(a.x, a.y), pack2(a.z, a.w),
                                               pack2(b.x, b.y), pack2(b.z, b.w));
        } else {
            // ---- fill rows 6144..6271: row 6144 = 1.0, rest = 0 ----
            const int f = u - CVT_TOTAL;
            size_t i = (size_t)f * 2048 + (size_t)tid * 8;     // offset in fill region
            uint32_t w0 = (i < NN) ? 0x3F803F80u : 0u;         // 6144 % 8 == 0: no straddle
            *(uint4*)(&g_adjb[(size_t)NN * NN + i]) = make_uint4(w0, w0, w0, w0);
        }
        return;
    }

    // ---- h = x @ W + Wb for (head, rows m0..m0+63), then scores + B tiles ----
    const int head = bx & 3;
    const int m0 = (bx >> 2) * 64;
    const int tx = tid & 15;
    const int ty = tid >> 4;

    float acc[4][4];
#pragma unroll
    for (int r = 0; r < 4; r++)
#pragma unroll
        for (int c = 0; c < 4; c++) acc[r][c] = 0.f;

    for (int k0 = 0; k0 < INF; k0 += 16) {
#pragma unroll
        for (int i = tid; i < 1024; i += 256) {
            int m = i >> 4, kk = i & 15;
            sA[kk][m] = x[(m0 + m) * INF + k0 + kk];
        }
#pragma unroll
        for (int i = tid; i < 1024; i += 256) {
            int kk = i >> 6, c = i & 63;
            sB[kk][c] = W[head * (INF * DHD) + (k0 + kk) * DHD + c];
        }
        __syncthreads();
#pragma unroll
        for (int kk = 0; kk < 16; kk++) {
            float4 av = *(const float4*)&sA[kk][ty * 4];
            float4 bv = *(const float4*)&sB[kk][tx * 4];
            float a4[4] = {av.x, av.y, av.z, av.w};
            float b4[4] = {bv.x, bv.y, bv.z, bv.w};
#pragma unroll
            for (int r = 0; r < 4; r++)
#pragma unroll
                for (int c = 0; c < 4; c++) acc[r][c] += a4[r] * b4[c];
        }
        __syncthreads();
    }

    // add bias into registers (h = acc + Wb)
#pragma unroll
    for (int c = 0; c < 4; c++) {
        float wb = Wb[head * DHD + tx * 4 + c];
#pragma unroll
        for (int r = 0; r < 4; r++) acc[r][c] += wb;
    }

    // partial score dots per thread
    {
        const float* Ah = A + head * 2 * DHD;
        float as[4], ad[4];
#pragma unroll
        for (int c = 0; c < 4; c++) {
            as[c] = Ah[tx * 4 + c];
            ad[c] = Ah[DHD + tx * 4 + c];
        }
#pragma unroll
        for (int r = 0; r < 4; r++) {
            float ps = 0.f, pd = 0.f;
#pragma unroll
            for (int c = 0; c < 4; c++) {
                ps += acc[r][c] * as[c];
                pd += acc[r][c] * ad[c];
            }
            sps[ty * 4 + r][tx] = ps;
            spd[ty * 4 + r][tx] = pd;
        }
    }
    __syncthreads();

    // row threads: finish scores, write esrc, esdst col of B
    if (tid < 64) {
        float ps = 0.f, pd = 0.f;
#pragma unroll
        for (int j = 0; j < 16; j++) {
            ps += sps[tid][j];
            pd += spd[tid][j];
        }
        const float esr = expf(ps + Ab[head]);
        const float esd = expf(pd);
        const int k = m0 + tid;
        g_esrc[head][k] = esr;
        sesd[tid] = esd;
        __nv_bfloat16 dhi = __float2bfloat16(esd);
        g_Bhi[k][512 + head] = dhi;
        g_Blo[k][512 + head] = __float2bfloat16(esd - __bfloat162float(dhi));
        if (head == 0) {
            g_Bhi[k][516] = __float2bfloat16(1.0f);
            g_Blo[k][516] = __float2bfloat16(0.0f);
        }
    }
    __syncthreads();

    // B main tiles: cols [head*64, +64) = esd*h (hi/lo), cols [256+head*64, +64) = h (hi/lo)
#pragma unroll
    for (int r = 0; r < 4; r++) {
        const int k = m0 + ty * 4 + r;
        const float esd = sesd[ty * 4 + r];
        float v1[4], v2[4], l1[4], l2[4];
#pragma unroll
        for (int c = 0; c < 4; c++) {
            v2[c] = acc[r][c];
            v1[c] = esd * acc[r][c];
            l1[c] = v1[c] - __bfloat162float(__float2bfloat16(v1[c]));
            l2[c] = v2[c] - __bfloat162float(__float2bfloat16(v2[c]));
        }
        uint2 hi1 = make_uint2(packbf2(v1[0], v1[1]), packbf2(v1[2], v1[3]));
        uint2 lo1 = make_uint2(packbf2(l1[0], l1[1]), packbf2(l1[2], l1[3]));
        uint2 hi2 = make_uint2(packbf2(v2[0], v2[1]), packbf2(v2[2], v2[3]));
        uint2 lo2 = make_uint2(packbf2(l2[0], l2[1]), packbf2(l2[2], l2[3]));
        *(uint2*)&g_Bhi[k][head * 64 + tx * 4]       = hi1;
        *(uint2*)&g_Blo[k][head * 64 + tx * 4]       = lo1;
        *(uint2*)&g_Bhi[k][256 + head * 64 + tx * 4] = hi2;
        *(uint2*)&g_Blo[k][256 + head * 64 + tx * 4] = lo2;
    }
}

// ---------------- K2: pipelined wmma GEMM (round-6 frozen; grid y = 49) ----------------
__device__ __forceinline__ void load_stage(uint32_t sb, int s, int k0, int m0, int n0,
                                           const __nv_bfloat16* __restrict__ adjb, int tid) {
    const uint32_t a_base  = sb + s * STAGE_BYTES;
    const uint32_t bh_base = a_base + A_BYTES;
    const uint32_t bl_base = bh_base + B_BYTES;
#pragma unroll
    for (int q = 0; q < 4; q++) {
        int idx = tid + q * 256;
        int row = idx >> 3, c = idx & 7;
        cp16(a_base + row * (A_LD * 2) + c * 16,
             adjb + (size_t)(m0 + row) * NN + k0 + c * 8);
    }
#pragma unroll
    for (int q = 0; q < 6; q++) {
        int idx = tid + q * 256;
        int row = idx / 24, c = idx - row * 24;
        cp16(bh_base + row * (B_LD * 2) + c * 16, &g_Bhi[k0 + row][n0 + c * 8]);
    }
#pragma unroll
    for (int q = 0; q < 6; q++) {
        int idx = tid + q * 256;
        int row = idx / 24, c = idx - row * 24;
        cp16(bl_base + row * (B_LD * 2) + c * 16, &g_Blo[k0 + row][n0 + c * 8]);
    }
    asm volatile("cp.async.commit_group;" ::: "memory");
}

__global__ void __launch_bounds__(GTHREADS, 1) k_attn_gemm(const __nv_bfloat16* __restrict__ adjb) {
    extern __shared__ char smem[];
    const uint32_t sb = smem_u32(smem);
    const int tid = threadIdx.x;
    const int wid = tid >> 5;
    const int wm = wid >> 2;          // 0..1  (64 rows each)
    const int wn = wid & 3;           // 0..3  (48 cols each)
    const int n0 = blockIdx.x * BN;
    const int m0 = blockIdx.y * BM;

    wmma::fragment<wmma::accumulator, 16, 16, 16, float> acc[4][3];
#pragma unroll
    for (int r = 0; r < 4; r++)
#pragma unroll
        for (int c = 0; c < 3; c++) wmma::fill_fragment(acc[r][c], 0.f);

    load_stage(sb, 0, 0, m0, n0, adjb, tid);
    load_stage(sb, 1, BK, m0, n0, adjb, tid);

    for (int i = 0; i < KITERS; i++) {
        const int s = i % STAGES;

        asm volatile("cp.async.wait_group 1;" ::: "memory");
        __syncthreads();
        if (i + 2 < KITERS)
            load_stage(sb, (i + 2) % STAGES, (i + 2) * BK, m0, n0, adjb, tid);
        else
            asm volatile("cp.async.commit_group;" ::: "memory");

        const __nv_bfloat16* sA  = (const __nv_bfloat16*)(smem + s * STAGE_BYTES);
        const __nv_bfloat16* sBh = (const __nv_bfloat16*)(smem + s * STAGE_BYTES + A_BYTES);
        const __nv_bfloat16* sBl = (const __nv_bfloat16*)(smem + s * STAGE_BYTES + A_BYTES + B_BYTES);

#pragma unroll
        for (int kk = 0; kk < BK / 16; kk++) {
            wmma::fragment<wmma::matrix_a, 16, 16, 16, __nv_bfloat16, wmma::row_major> af[4];
#pragma unroll
            for (int r = 0; r < 4; r++)
                wmma::load_matrix_sync(af[r], sA + (wm * 64 + r * 16) * A_LD + kk * 16, A_LD);
#pragma unroll
            for (int c = 0; c < 3; c++) {
                wmma::fragment<wmma::matrix_b, 16, 16, 16, __nv_bfloat16, wmma::row_major> bf;
                wmma::load_matrix_sync(bf, sBh + (kk * 16) * B_LD + wn * 48 + c * 16, B_LD);
#pragma unroll
                for (int r = 0; r < 4; r++) wmma::mma_sync(acc[r][c], af[r], bf, acc[r][c]);
                wmma::load_matrix_sync(bf, sBl + (kk * 16) * B_LD + wn * 48 + c * 16, B_LD);
#pragma unroll
                for (int r = 0; r < 4; r++) wmma::mma_sync(acc[r][c], af[r], bf, acc[r][c]);
            }
        }
    }

#pragma unroll
    for (int r = 0; r < 4; r++)
#pragma unroll
        for (int c = 0; c < 3; c++)
            wmma::store_matrix_sync(&g_C[m0 + wm * 64 + r * 16][n0 + wn * 48 + c * 16],
                                    acc[r][c], NCOLS, wmma::mem_row_major);
}

// ---------------- K3: epilogue (float4; T from GEMM ones-row) ----------------
__global__ void k_epi(float* __restrict__ out) {
    const int t = blockIdx.x * 256 + threadIdx.x;   // over NN*64 (4 cols each)
    const int n = t >> 6;
    const int c4 = (t & 63) * 4;
    const int hd = c4 >> 6;
    const float es  = g_esrc[hd][n];
    const float4 u  = *(const float4*)&g_C[n][c4];
    const float4 v  = *(const float4*)&g_C[n][256 + c4];
    const float4 T  = *(const float4*)&g_C[NN][256 + c4];   // ones-row @ B = colsum(h)
    const float w   = g_C[n][512 + hd];
    const float deg = g_C[n][516];
    const float invZ = 1.0f / (es * w + ((float)NN - deg));
    float4 o;
    o.x = (es * u.x + T.x - v.x) * invZ;
    o.y = (es * u.y + T.y - v.y) * invZ;
    o.z = (es * u.z + T.z - v.z) * invZ;
    o.w = (es * u.w + T.w - v.w) * invZ;
    *(float4*)&out[n * HD + c4] = o;
}

// ---------------- launch ----------------
extern "C" void kernel_launch(void* const* d_in, const int* in_sizes, int n_in,
                              void* d_out, int out_size) {
    const float* x = nullptr; const int* adj = nullptr;
    const float* W = nullptr; const float* Wb = nullptr;
    const float* A = nullptr; const float* Ab = nullptr;
    for (int i = 0; i < n_in; i++) {
        switch (in_sizes[i]) {
            case NN * INF:        x   = (const float*)d_in[i]; break;
            case NH * INF * DHD:  W   = (const float*)d_in[i]; break;
            case NH * DHD:        Wb  = (const float*)d_in[i]; break;
            case NH * 2 * DHD:    A   = (const float*)d_in[i]; break;
            case NH:              Ab  = (const float*)d_in[i]; break;
            default:
                if (in_sizes[i] == NN * NN) adj = (const int*)d_in[i];
                break;
        }
    }
    float* out = (float*)d_out;

    cudaFuncSetAttribute(k_attn_gemm, cudaFuncAttributeMaxDynamicSharedMemorySize, SMEM_BYTES);

    __nv_bfloat16* adjb_ptr = nullptr;
    cudaGetSymbolAddress((void**)&adjb_ptr, g_adjb);

    k_pre<<<HBLOCKS + CVT_TOTAL + FILL_TOTAL, 256>>>(x, W, Wb, A, Ab, adj);
    k_attn_gemm<<<dim3(NCOLS / BN, MROWS / BM), GTHREADS, SMEM_BYTES>>>(adjb_ptr);
    k_epi<<<(NN * 64) / 256, 256>>>(out);
}